// round 15
// baseline (speedup 1.0000x reference)
#include <cuda_runtime.h>
#include <mma.h>
#include <math.h>

using namespace nvcuda;

#define N_V    100000
#define NE_    20000
#define NNZ_   1600000
#define NFEAT_ 128
#define NHID_  64
#define NCLASS_ 40
#define NLAYER_ 4

// ---------------- device scratch (static, no allocation) ----------------
__device__ float g_X [N_V * NHID_];   // current features (GEMM output)
__device__ float g_Xi[N_V * NHID_];   // Xi staging (agg_ev output) -> GEMM input
__device__ float g_X0[N_V * NHID_];   // residual anchor
__device__ float g_Xe[NE_ * NHID_];   // edge features (pre-scaled by degE/count)
__device__ float g_escale[NE_];
__device__ int   g_cntE[NE_];         // hist counts -> then bump cursors
__device__ int   g_cntV[N_V];
__device__ int   g_lenE[NE_];
__device__ int   g_lenV[N_V];
__device__ int   g_offE[NE_];
__device__ int   g_offV[N_V];
__device__ int   g_curE;
__device__ int   g_curV;
__device__ int   g_adjE[NNZ_];
__device__ int   g_adjV[NNZ_];

// ---------------- CSR build ----------------
__global__ void zero_cnt_k() {
    int i = blockIdx.x * blockDim.x + threadIdx.x;
    if (i < NE_) g_cntE[i] = 0;
    if (i < N_V) g_cntV[i] = 0;
    if (i == 0) { g_curE = 0; g_curV = 0; }
}

__global__ void hist_k(const int4* __restrict__ vertex4, const int4* __restrict__ edges4) {
    int i = blockIdx.x * blockDim.x + threadIdx.x;
    if (i < NNZ_ / 8) {
        int4 e0 = edges4[i * 2], e1 = edges4[i * 2 + 1];
        int4 v0 = vertex4[i * 2], v1 = vertex4[i * 2 + 1];
        atomicAdd(&g_cntE[e0.x], 1); atomicAdd(&g_cntE[e0.y], 1);
        atomicAdd(&g_cntE[e0.z], 1); atomicAdd(&g_cntE[e0.w], 1);
        atomicAdd(&g_cntE[e1.x], 1); atomicAdd(&g_cntE[e1.y], 1);
        atomicAdd(&g_cntE[e1.z], 1); atomicAdd(&g_cntE[e1.w], 1);
        atomicAdd(&g_cntV[v0.x], 1); atomicAdd(&g_cntV[v0.y], 1);
        atomicAdd(&g_cntV[v0.z], 1); atomicAdd(&g_cntV[v0.w], 1);
        atomicAdd(&g_cntV[v1.x], 1); atomicAdd(&g_cntV[v1.y], 1);
        atomicAdd(&g_cntV[v1.z], 1); atomicAdd(&g_cntV[v1.w], 1);
    }
}

__global__ void alloc_k(const float* __restrict__ degE) {
    int i = blockIdx.x * blockDim.x + threadIdx.x;
    const int n = NE_ + N_V;
    if (i >= n) return;
    int lane = threadIdx.x & 31;
    bool isE = (i < NE_);
    int c = isE ? g_cntE[i] : g_cntV[i - NE_];
    int inc = c;
    #pragma unroll
    for (int o = 1; o < 32; o <<= 1) {
        int t = __shfl_up_sync(0xffffffffu, inc, o);
        if (lane >= o) inc += t;
    }
    int base = 0;
    if (lane == 31)
        base = atomicAdd(isE ? &g_curE : &g_curV, inc);
    base = __shfl_sync(0xffffffffu, base, 31);
    int off = base + inc - c;
    if (isE) {
        g_offE[i] = off;
        g_lenE[i] = c;
        g_escale[i] = degE[i] / fmaxf((float)c, 1.0f);
        g_cntE[i] = off;
    } else {
        g_offV[i - NE_] = off;
        g_lenV[i - NE_] = c;
        g_cntV[i - NE_] = off;
    }
}

__global__ void build_adj_k(const int4* __restrict__ vertex4, const int4* __restrict__ edges4) {
    int i = blockIdx.x * blockDim.x + threadIdx.x;
    if (i < NNZ_ / 8) {
        int4 v0 = vertex4[i * 2], v1 = vertex4[i * 2 + 1];
        int4 e0 = edges4[i * 2],  e1 = edges4[i * 2 + 1];
        int pe0 = atomicAdd(&g_cntE[e0.x], 1);
        int pe1 = atomicAdd(&g_cntE[e0.y], 1);
        int pe2 = atomicAdd(&g_cntE[e0.z], 1);
        int pe3 = atomicAdd(&g_cntE[e0.w], 1);
        int pe4 = atomicAdd(&g_cntE[e1.x], 1);
        int pe5 = atomicAdd(&g_cntE[e1.y], 1);
        int pe6 = atomicAdd(&g_cntE[e1.z], 1);
        int pe7 = atomicAdd(&g_cntE[e1.w], 1);
        int pv0 = atomicAdd(&g_cntV[v0.x], 1);
        int pv1 = atomicAdd(&g_cntV[v0.y], 1);
        int pv2 = atomicAdd(&g_cntV[v0.z], 1);
        int pv3 = atomicAdd(&g_cntV[v0.w], 1);
        int pv4 = atomicAdd(&g_cntV[v1.x], 1);
        int pv5 = atomicAdd(&g_cntV[v1.y], 1);
        int pv6 = atomicAdd(&g_cntV[v1.z], 1);
        int pv7 = atomicAdd(&g_cntV[v1.w], 1);
        g_adjE[pe0] = v0.x; g_adjE[pe1] = v0.y; g_adjE[pe2] = v0.z; g_adjE[pe3] = v0.w;
        g_adjE[pe4] = v1.x; g_adjE[pe5] = v1.y; g_adjE[pe6] = v1.z; g_adjE[pe7] = v1.w;
        g_adjV[pv0] = e0.x; g_adjV[pv1] = e0.y; g_adjV[pv2] = e0.z; g_adjV[pv3] = e0.w;
        g_adjV[pv4] = e1.x; g_adjV[pv5] = e1.y; g_adjV[pv6] = e1.z; g_adjV[pv7] = e1.w;
    }
}

// ---------------- vertex -> edge mean (warp per edge, float2 lanes) ----------------
__global__ void __launch_bounds__(256) agg_ve_k() {
    int e = blockIdx.x * 8 + (threadIdx.x >> 5);
    if (e >= NE_) return;
    int lane = threadIdx.x & 31;
    int beg = g_offE[e], len = g_lenE[e];
    float ax = 0.f, ay = 0.f;
    const float* __restrict__ X = g_X;
    int j = 0;
    for (; j + 8 <= len; j += 8) {
        int i0 = g_adjE[beg + j + 0], i1 = g_adjE[beg + j + 1];
        int i2 = g_adjE[beg + j + 2], i3 = g_adjE[beg + j + 3];
        int i4 = g_adjE[beg + j + 4], i5 = g_adjE[beg + j + 5];
        int i6 = g_adjE[beg + j + 6], i7 = g_adjE[beg + j + 7];
        float2 t0 = __ldg((const float2*)&X[i0 * NHID_ + lane * 2]);
        float2 t1 = __ldg((const float2*)&X[i1 * NHID_ + lane * 2]);
        float2 t2 = __ldg((const float2*)&X[i2 * NHID_ + lane * 2]);
        float2 t3 = __ldg((const float2*)&X[i3 * NHID_ + lane * 2]);
        float2 t4 = __ldg((const float2*)&X[i4 * NHID_ + lane * 2]);
        float2 t5 = __ldg((const float2*)&X[i5 * NHID_ + lane * 2]);
        float2 t6 = __ldg((const float2*)&X[i6 * NHID_ + lane * 2]);
        float2 t7 = __ldg((const float2*)&X[i7 * NHID_ + lane * 2]);
        ax += ((t0.x + t1.x) + (t2.x + t3.x)) + ((t4.x + t5.x) + (t6.x + t7.x));
        ay += ((t0.y + t1.y) + (t2.y + t3.y)) + ((t4.y + t5.y) + (t6.y + t7.y));
    }
    for (; j < len; j++) {
        int v = g_adjE[beg + j];
        float2 t = __ldg((const float2*)&X[v * NHID_ + lane * 2]);
        ax += t.x; ay += t.y;
    }
    float s = g_escale[e];
    float2 r; r.x = ax * s; r.y = ay * s;
    *(float2*)&g_Xe[e * NHID_ + lane * 2] = r;
}

// ---------------- edge -> vertex sum, *degV, L2 norm, alpha-mix -> g_Xi ----------------
__global__ void __launch_bounds__(256) agg_ev_k(const float* __restrict__ degV) {
    int v = blockIdx.x * 8 + (threadIdx.x >> 5);
    if (v >= N_V) return;
    int lane = threadIdx.x & 31;
    int beg = g_offV[v], len = g_lenV[v];
    float ax = 0.f, ay = 0.f;
    const float* __restrict__ Xe = g_Xe;
    int j = 0;
    for (; j + 8 <= len; j += 8) {
        int e0 = g_adjV[beg + j + 0], e1 = g_adjV[beg + j + 1];
        int e2 = g_adjV[beg + j + 2], e3 = g_adjV[beg + j + 3];
        int e4 = g_adjV[beg + j + 4], e5 = g_adjV[beg + j + 5];
        int e6 = g_adjV[beg + j + 6], e7 = g_adjV[beg + j + 7];
        float2 t0 = __ldg((const float2*)&Xe[e0 * NHID_ + lane * 2]);
        float2 t1 = __ldg((const float2*)&Xe[e1 * NHID_ + lane * 2]);
        float2 t2 = __ldg((const float2*)&Xe[e2 * NHID_ + lane * 2]);
        float2 t3 = __ldg((const float2*)&Xe[e3 * NHID_ + lane * 2]);
        float2 t4 = __ldg((const float2*)&Xe[e4 * NHID_ + lane * 2]);
        float2 t5 = __ldg((const float2*)&Xe[e5 * NHID_ + lane * 2]);
        float2 t6 = __ldg((const float2*)&Xe[e6 * NHID_ + lane * 2]);
        float2 t7 = __ldg((const float2*)&Xe[e7 * NHID_ + lane * 2]);
        ax += ((t0.x + t1.x) + (t2.x + t3.x)) + ((t4.x + t5.x) + (t6.x + t7.x));
        ay += ((t0.y + t1.y) + (t2.y + t3.y)) + ((t4.y + t5.y) + (t6.y + t7.y));
    }
    for (; j < len; j++) {
        int e = g_adjV[beg + j];
        float2 t = __ldg((const float2*)&Xe[e * NHID_ + lane * 2]);
        ax += t.x; ay += t.y;
    }
    float dv = __ldg(&degV[v]);
    ax *= dv; ay *= dv;
    float ss = ax * ax + ay * ay;
    #pragma unroll
    for (int o = 16; o; o >>= 1) ss += __shfl_xor_sync(0xffffffffu, ss, o);
    float scale = (ss > 0.f) ? rsqrtf(ss) : 0.f;
    float2 x0 = *(const float2*)&g_X0[(size_t)v * NHID_ + lane * 2];
    float2 r;
    r.x = 0.9f * ax * scale + 0.1f * x0.x;
    r.y = 0.9f * ay * scale + 0.1f * x0.y;
    *(float2*)&g_Xi[(size_t)v * NHID_ + lane * 2] = r;
}

// ---------------- tensor-core GEMM (wmma, fp16 in / fp32 accum) ----------------
// 256 threads (8 warps), 128-row x 64-col tile; warp wid owns row-tile wid
// (16 rows) x all 4 col-tiles (4 accumulator fragments).
// MODE 0: g_X = relu(x@W0 + b), copy to g_X0.  (A = Aext fp32, K=128)
// MODE 1: g_X = relu(c0*Xi + c1*(Xi@W)).        (A = g_Xi fp32, K=64)
template <int K, int MODE>
__global__ void __launch_bounds__(256) tc_gemm_k(
    const float* __restrict__ Aext, const float* __restrict__ W,
    const float* __restrict__ bias, float c0, float c1)
{
    constexpr int ROWS = 128;
    constexpr int KP  = K + 8;          // half lds (mult of 8)
    constexpr int WLD = 72;             // W lds (mult of 8)
    constexpr int CLD = 68;             // C lds floats (mult of 4)
    constexpr int AW_BYTES = ROWS * KP * 2 + K * WLD * 2;
    constexpr int C_BYTES  = ROWS * CLD * 4;
    constexpr int S_BYTES  = (AW_BYTES > C_BYTES) ? AW_BYTES : C_BYTES;
    __shared__ __align__(16) unsigned char sbuf[S_BYTES];
    __half* Ash = (__half*)sbuf;
    __half* Wsh = (__half*)(sbuf + ROWS * KP * 2);
    float*  Csh = (float*)sbuf;         // aliases Ash/Wsh AFTER the mma loop

    const float* A = (MODE == 0) ? Aext : g_Xi;
    int tid = threadIdx.x;
    int wid = tid >> 5;
    int row0 = blockIdx.x * ROWS;

    // Stage A (fp32 -> fp16), ROWS x K
    for (int idx = tid; idx < ROWS * (K / 4); idx += 256) {
        int r = idx / (K / 4), c4 = idx - r * (K / 4);
        int row = row0 + r;
        float4 v = make_float4(0.f, 0.f, 0.f, 0.f);
        if (row < N_V) v = *(const float4*)&A[(size_t)row * K + c4 * 4];
        __half2 h0 = __floats2half2_rn(v.x, v.y);
        __half2 h1 = __floats2half2_rn(v.z, v.w);
        *(uint2*)&Ash[r * KP + c4 * 4] = make_uint2(*(unsigned*)&h0, *(unsigned*)&h1);
    }
    // Stage W (fp32 -> fp16), K x 64
    for (int idx = tid; idx < K * 16; idx += 256) {
        int k = idx >> 4, c4 = idx & 15;
        float4 v = *(const float4*)&W[k * 64 + c4 * 4];
        __half2 h0 = __floats2half2_rn(v.x, v.y);
        __half2 h1 = __floats2half2_rn(v.z, v.w);
        *(uint2*)&Wsh[k * WLD + c4 * 4] = make_uint2(*(unsigned*)&h0, *(unsigned*)&h1);
    }
    __syncthreads();

    wmma::fragment<wmma::accumulator, 16, 16, 16, float> cf[4];
    #pragma unroll
    for (int c = 0; c < 4; c++) wmma::fill_fragment(cf[c], 0.f);
    #pragma unroll
    for (int kk = 0; kk < K; kk += 16) {
        wmma::fragment<wmma::matrix_a, 16, 16, 16, __half, wmma::row_major> af;
        wmma::load_matrix_sync(af, Ash + wid * 16 * KP + kk, KP);
        #pragma unroll
        for (int c = 0; c < 4; c++) {
            wmma::fragment<wmma::matrix_b, 16, 16, 16, __half, wmma::row_major> bf;
            wmma::load_matrix_sync(bf, Wsh + kk * WLD + c * 16, WLD);
            wmma::mma_sync(cf[c], af, bf, cf[c]);
        }
    }
    __syncthreads();   // done reading Ash/Wsh; safe to alias Csh

    #pragma unroll
    for (int c = 0; c < 4; c++)
        wmma::store_matrix_sync(Csh + wid * 16 * CLD + c * 16, cf[c], CLD, wmma::mem_row_major);
    __syncthreads();

    // fp32 epilogue (ROWS x 16 float4-groups over 256 threads)
    for (int idx = tid; idx < ROWS * 16; idx += 256) {
        int r = idx >> 4, c4 = idx & 15;
        int row = row0 + r;
        if (row >= N_V) continue;
        float4 cv = *(float4*)&Csh[r * CLD + c4 * 4];
        float4 o;
        if (MODE == 0) {
            float4 b = *(const float4*)&bias[c4 * 4];
            o.x = fmaxf(cv.x + b.x, 0.f);
            o.y = fmaxf(cv.y + b.y, 0.f);
            o.z = fmaxf(cv.z + b.z, 0.f);
            o.w = fmaxf(cv.w + b.w, 0.f);
            *(float4*)&g_X [(size_t)row * NHID_ + c4 * 4] = o;
            *(float4*)&g_X0[(size_t)row * NHID_ + c4 * 4] = o;
        } else {
            float4 xi = *(const float4*)&g_Xi[(size_t)row * NHID_ + c4 * 4];
            o.x = fmaxf(c0 * xi.x + c1 * cv.x, 0.f);
            o.y = fmaxf(c0 * xi.y + c1 * cv.y, 0.f);
            o.z = fmaxf(c0 * xi.z + c1 * cv.z, 0.f);
            o.w = fmaxf(c0 * xi.w + c1 * cv.w, 0.f);
            *(float4*)&g_X[(size_t)row * NHID_ + c4 * 4] = o;
        }
    }
}

// ---------------- fp32 output GEMM (kept for logits accuracy) ----------------
// out = log_softmax(g_X @ Wout + bout), K=64, NCOL=40
__global__ void __launch_bounds__(128) gemm_out_k(
    const float* __restrict__ W, const float* __restrict__ bias,
    float* __restrict__ outext)
{
    constexpr int K = 64, NCOL = 40;
    constexpr int KP = K + 4;
    constexpr int NP = 44;
    __shared__ __align__(16) float As[64 * KP];
    __shared__ __align__(16) float Wsm[K * NP];
    __shared__ float Ls[64 * NCOL];

    const float* A = g_X;
    int tid = threadIdx.x;
    int row0 = blockIdx.x * 64;
    int tx = tid & 7;
    int ty = tid >> 3;
    bool active = (tx * 8 < NCOL);

    float acc[4][8] = {};

    for (int idx = tid; idx < K * (NCOL / 4); idx += 128) {
        int k = idx / (NCOL / 4), c4 = idx - k * (NCOL / 4);
        *(float4*)&Wsm[k * NP + c4 * 4] = *(const float4*)&W[k * NCOL + c4 * 4];
    }
    for (int idx = tid; idx < 64 * (K / 4); idx += 128) {
        int r = idx / (K / 4), k4 = idx - r * (K / 4);
        int row = row0 + r;
        float4 v = make_float4(0.f, 0.f, 0.f, 0.f);
        if (row < N_V) v = *(const float4*)&A[(size_t)row * K + k4 * 4];
        *(float4*)&As[r * KP + k4 * 4] = v;
    }
    __syncthreads();
    if (active) {
        #pragma unroll 4
        for (int k = 0; k < K; k++) {
            float4 w0 = *(const float4*)&Wsm[k * NP + tx * 8];
            float4 w1 = *(const float4*)&Wsm[k * NP + tx * 8 + 4];
            #pragma unroll
            for (int i = 0; i < 4; i++) {
                float a = As[(ty * 4 + i) * KP + k];
                acc[i][0] += a * w0.x; acc[i][1] += a * w0.y;
                acc[i][2] += a * w0.z; acc[i][3] += a * w0.w;
                acc[i][4] += a * w1.x; acc[i][5] += a * w1.y;
                acc[i][6] += a * w1.z; acc[i][7] += a * w1.w;
            }
        }
        #pragma unroll
        for (int i = 0; i < 4; i++) {
            int r = ty * 4 + i;
            #pragma unroll
            for (int j = 0; j < 8; j++)
                Ls[r * NCOL + tx * 8 + j] = acc[i][j] + __ldg(bias + tx * 8 + j);
        }
    }
    __syncthreads();
    if (tid < 64) {
        int row = row0 + tid;
        if (row < N_V) {
            float mx = -1e30f;
            #pragma unroll
            for (int c = 0; c < NCOL; c++) mx = fmaxf(mx, Ls[tid * NCOL + c]);
            float s = 0.f;
            #pragma unroll
            for (int c = 0; c < NCOL; c++) s += __expf(Ls[tid * NCOL + c] - mx);
            float lse = mx + __logf(s);
            #pragma unroll
            for (int c = 0; c < NCOL; c++)
                outext[(size_t)row * NCOL + c] = Ls[tid * NCOL + c] - lse;
        }
    }
}

// ---------------- launch ----------------
extern "C" void kernel_launch(void* const* d_in, const int* in_sizes, int n_in,
                              void* d_out, int out_size)
{
    const float* x    = (const float*)d_in[0];
    const float* degE = (const float*)d_in[1];
    const float* degV = (const float*)d_in[2];
    const float* W0   = (const float*)d_in[3];
    const float* b0   = (const float*)d_in[4];
    const float* Ws   = (const float*)d_in[5];
    const float* Wout = (const float*)d_in[6];
    const float* bout = (const float*)d_in[7];
    const int* vertex = (const int*)d_in[8];
    const int* edges  = (const int*)d_in[9];
    float* out = (float*)d_out;

    (void)in_sizes; (void)n_in; (void)out_size;

    const int GB64  = (N_V + 63) / 64;
    const int GB128 = (N_V + 127) / 128;
    const int Q8 = NNZ_ / 8;

    // CSR/CSC build
    zero_cnt_k<<<(N_V + 255) / 256, 256>>>();
    hist_k<<<(Q8 + 255) / 256, 256>>>((const int4*)vertex, (const int4*)edges);
    alloc_k<<<(NE_ + N_V + 255) / 256, 256>>>(degE);
    build_adj_k<<<(Q8 + 255) / 256, 256>>>((const int4*)vertex, (const int4*)edges);

    // X = relu(x @ W0 + b0); X0 = X   (tensor core, 128-row tiles)
    tc_gemm_k<128, 0><<<GB128, 256>>>(x, W0, b0, 0.f, 0.f);

    for (int i = 0; i < NLAYER_; i++) {
        float beta = logf(0.5f / (float)(i + 1) + 1.0f);
        agg_ve_k<<<(NE_ + 7) / 8, 256>>>();
        agg_ev_k<<<(N_V + 7) / 8, 256>>>(degV);
        tc_gemm_k<64, 1><<<GB128, 256>>>(nullptr, Ws + (size_t)i * NHID_ * NHID_,
                                         nullptr, 1.0f - beta, beta);
    }

    // log_softmax(X @ Wout + bout)  (fp32 for logits accuracy)
    gemm_out_k<<<GB64, 128>>>(Wout, bout, out);
}

// round 16
// speedup vs baseline: 1.0797x; 1.0797x over previous
#include <cuda_runtime.h>
#include <mma.h>
#include <math.h>

using namespace nvcuda;

#define N_V    100000
#define NE_    20000
#define NNZ_   1600000
#define NFEAT_ 128
#define NHID_  64
#define NCLASS_ 40
#define NLAYER_ 4

// ---------------- device scratch (static, no allocation) ----------------
__device__ float g_X [N_V * NHID_];   // current features (GEMM output)
__device__ float g_Xi[N_V * NHID_];   // Xi staging (agg_ev output) -> GEMM input
__device__ float g_X0[N_V * NHID_];   // residual anchor
__device__ float g_Xe[NE_ * NHID_];   // edge features (pre-scaled by degE/count)
__device__ float g_escale[NE_];
__device__ int   g_cntE[NE_];         // hist counts -> then bump cursors
__device__ int   g_cntV[N_V];
__device__ int   g_lenE[NE_];
__device__ int   g_lenV[N_V];
__device__ int   g_offE[NE_];
__device__ int   g_offV[N_V];
__device__ int   g_curE;
__device__ int   g_curV;
__device__ int   g_adjE[NNZ_];
__device__ int   g_adjV[NNZ_];

// ---------------- CSR build ----------------
__global__ void zero_cnt_k() {
    int i = blockIdx.x * blockDim.x + threadIdx.x;
    if (i < NE_) g_cntE[i] = 0;
    if (i < N_V) g_cntV[i] = 0;
    if (i == 0) { g_curE = 0; g_curV = 0; }
}

__global__ void hist_k(const int4* __restrict__ vertex4, const int4* __restrict__ edges4) {
    int i = blockIdx.x * blockDim.x + threadIdx.x;
    if (i < NNZ_ / 8) {
        int4 e0 = edges4[i * 2], e1 = edges4[i * 2 + 1];
        int4 v0 = vertex4[i * 2], v1 = vertex4[i * 2 + 1];
        atomicAdd(&g_cntE[e0.x], 1); atomicAdd(&g_cntE[e0.y], 1);
        atomicAdd(&g_cntE[e0.z], 1); atomicAdd(&g_cntE[e0.w], 1);
        atomicAdd(&g_cntE[e1.x], 1); atomicAdd(&g_cntE[e1.y], 1);
        atomicAdd(&g_cntE[e1.z], 1); atomicAdd(&g_cntE[e1.w], 1);
        atomicAdd(&g_cntV[v0.x], 1); atomicAdd(&g_cntV[v0.y], 1);
        atomicAdd(&g_cntV[v0.z], 1); atomicAdd(&g_cntV[v0.w], 1);
        atomicAdd(&g_cntV[v1.x], 1); atomicAdd(&g_cntV[v1.y], 1);
        atomicAdd(&g_cntV[v1.z], 1); atomicAdd(&g_cntV[v1.w], 1);
    }
}

__global__ void alloc_k(const float* __restrict__ degE) {
    int i = blockIdx.x * blockDim.x + threadIdx.x;
    const int n = NE_ + N_V;
    if (i >= n) return;
    int lane = threadIdx.x & 31;
    bool isE = (i < NE_);
    int c = isE ? g_cntE[i] : g_cntV[i - NE_];
    int inc = c;
    #pragma unroll
    for (int o = 1; o < 32; o <<= 1) {
        int t = __shfl_up_sync(0xffffffffu, inc, o);
        if (lane >= o) inc += t;
    }
    int base = 0;
    if (lane == 31)
        base = atomicAdd(isE ? &g_curE : &g_curV, inc);
    base = __shfl_sync(0xffffffffu, base, 31);
    int off = base + inc - c;
    if (isE) {
        g_offE[i] = off;
        g_lenE[i] = c;
        g_escale[i] = degE[i] / fmaxf((float)c, 1.0f);
        g_cntE[i] = off;
    } else {
        g_offV[i - NE_] = off;
        g_lenV[i - NE_] = c;
        g_cntV[i - NE_] = off;
    }
}

__global__ void build_adj_k(const int4* __restrict__ vertex4, const int4* __restrict__ edges4) {
    int i = blockIdx.x * blockDim.x + threadIdx.x;
    if (i < NNZ_ / 8) {
        int4 v0 = vertex4[i * 2], v1 = vertex4[i * 2 + 1];
        int4 e0 = edges4[i * 2],  e1 = edges4[i * 2 + 1];
        int pe0 = atomicAdd(&g_cntE[e0.x], 1);
        int pe1 = atomicAdd(&g_cntE[e0.y], 1);
        int pe2 = atomicAdd(&g_cntE[e0.z], 1);
        int pe3 = atomicAdd(&g_cntE[e0.w], 1);
        int pe4 = atomicAdd(&g_cntE[e1.x], 1);
        int pe5 = atomicAdd(&g_cntE[e1.y], 1);
        int pe6 = atomicAdd(&g_cntE[e1.z], 1);
        int pe7 = atomicAdd(&g_cntE[e1.w], 1);
        int pv0 = atomicAdd(&g_cntV[v0.x], 1);
        int pv1 = atomicAdd(&g_cntV[v0.y], 1);
        int pv2 = atomicAdd(&g_cntV[v0.z], 1);
        int pv3 = atomicAdd(&g_cntV[v0.w], 1);
        int pv4 = atomicAdd(&g_cntV[v1.x], 1);
        int pv5 = atomicAdd(&g_cntV[v1.y], 1);
        int pv6 = atomicAdd(&g_cntV[v1.z], 1);
        int pv7 = atomicAdd(&g_cntV[v1.w], 1);
        g_adjE[pe0] = v0.x; g_adjE[pe1] = v0.y; g_adjE[pe2] = v0.z; g_adjE[pe3] = v0.w;
        g_adjE[pe4] = v1.x; g_adjE[pe5] = v1.y; g_adjE[pe6] = v1.z; g_adjE[pe7] = v1.w;
        g_adjV[pv0] = e0.x; g_adjV[pv1] = e0.y; g_adjV[pv2] = e0.z; g_adjV[pv3] = e0.w;
        g_adjV[pv4] = e1.x; g_adjV[pv5] = e1.y; g_adjV[pv6] = e1.z; g_adjV[pv7] = e1.w;
    }
}

// ---------------- vertex -> edge mean (warp per edge, float2 lanes) ----------------
__global__ void __launch_bounds__(256) agg_ve_k() {
    int e = blockIdx.x * 8 + (threadIdx.x >> 5);
    if (e >= NE_) return;
    int lane = threadIdx.x & 31;
    int beg = g_offE[e], len = g_lenE[e];
    float ax = 0.f, ay = 0.f;
    const float* __restrict__ X = g_X;
    int j = 0;
    for (; j + 8 <= len; j += 8) {
        int i0 = g_adjE[beg + j + 0], i1 = g_adjE[beg + j + 1];
        int i2 = g_adjE[beg + j + 2], i3 = g_adjE[beg + j + 3];
        int i4 = g_adjE[beg + j + 4], i5 = g_adjE[beg + j + 5];
        int i6 = g_adjE[beg + j + 6], i7 = g_adjE[beg + j + 7];
        float2 t0 = __ldg((const float2*)&X[i0 * NHID_ + lane * 2]);
        float2 t1 = __ldg((const float2*)&X[i1 * NHID_ + lane * 2]);
        float2 t2 = __ldg((const float2*)&X[i2 * NHID_ + lane * 2]);
        float2 t3 = __ldg((const float2*)&X[i3 * NHID_ + lane * 2]);
        float2 t4 = __ldg((const float2*)&X[i4 * NHID_ + lane * 2]);
        float2 t5 = __ldg((const float2*)&X[i5 * NHID_ + lane * 2]);
        float2 t6 = __ldg((const float2*)&X[i6 * NHID_ + lane * 2]);
        float2 t7 = __ldg((const float2*)&X[i7 * NHID_ + lane * 2]);
        ax += ((t0.x + t1.x) + (t2.x + t3.x)) + ((t4.x + t5.x) + (t6.x + t7.x));
        ay += ((t0.y + t1.y) + (t2.y + t3.y)) + ((t4.y + t5.y) + (t6.y + t7.y));
    }
    for (; j < len; j++) {
        int v = g_adjE[beg + j];
        float2 t = __ldg((const float2*)&X[v * NHID_ + lane * 2]);
        ax += t.x; ay += t.y;
    }
    float s = g_escale[e];
    float2 r; r.x = ax * s; r.y = ay * s;
    *(float2*)&g_Xe[e * NHID_ + lane * 2] = r;
}

// ---------------- edge -> vertex sum, *degV, L2 norm, alpha-mix -> g_Xi ----------------
__global__ void __launch_bounds__(256) agg_ev_k(const float* __restrict__ degV) {
    int v = blockIdx.x * 8 + (threadIdx.x >> 5);
    if (v >= N_V) return;
    int lane = threadIdx.x & 31;
    int beg = g_offV[v], len = g_lenV[v];
    float ax = 0.f, ay = 0.f;
    const float* __restrict__ Xe = g_Xe;
    int j = 0;
    for (; j + 8 <= len; j += 8) {
        int e0 = g_adjV[beg + j + 0], e1 = g_adjV[beg + j + 1];
        int e2 = g_adjV[beg + j + 2], e3 = g_adjV[beg + j + 3];
        int e4 = g_adjV[beg + j + 4], e5 = g_adjV[beg + j + 5];
        int e6 = g_adjV[beg + j + 6], e7 = g_adjV[beg + j + 7];
        float2 t0 = __ldg((const float2*)&Xe[e0 * NHID_ + lane * 2]);
        float2 t1 = __ldg((const float2*)&Xe[e1 * NHID_ + lane * 2]);
        float2 t2 = __ldg((const float2*)&Xe[e2 * NHID_ + lane * 2]);
        float2 t3 = __ldg((const float2*)&Xe[e3 * NHID_ + lane * 2]);
        float2 t4 = __ldg((const float2*)&Xe[e4 * NHID_ + lane * 2]);
        float2 t5 = __ldg((const float2*)&Xe[e5 * NHID_ + lane * 2]);
        float2 t6 = __ldg((const float2*)&Xe[e6 * NHID_ + lane * 2]);
        float2 t7 = __ldg((const float2*)&Xe[e7 * NHID_ + lane * 2]);
        ax += ((t0.x + t1.x) + (t2.x + t3.x)) + ((t4.x + t5.x) + (t6.x + t7.x));
        ay += ((t0.y + t1.y) + (t2.y + t3.y)) + ((t4.y + t5.y) + (t6.y + t7.y));
    }
    for (; j < len; j++) {
        int e = g_adjV[beg + j];
        float2 t = __ldg((const float2*)&Xe[e * NHID_ + lane * 2]);
        ax += t.x; ay += t.y;
    }
    float dv = __ldg(&degV[v]);
    ax *= dv; ay *= dv;
    float ss = ax * ax + ay * ay;
    #pragma unroll
    for (int o = 16; o; o >>= 1) ss += __shfl_xor_sync(0xffffffffu, ss, o);
    float scale = (ss > 0.f) ? rsqrtf(ss) : 0.f;
    float2 x0 = *(const float2*)&g_X0[(size_t)v * NHID_ + lane * 2];
    float2 r;
    r.x = 0.9f * ax * scale + 0.1f * x0.x;
    r.y = 0.9f * ay * scale + 0.1f * x0.y;
    *(float2*)&g_Xi[(size_t)v * NHID_ + lane * 2] = r;
}

// ---------------- tensor-core GEMM (wmma, fp16 in / fp32 accum) ----------------
// 256 threads (8 warps), 64-row x 64-col tile, warp owns 2 adjacent 16x16 tiles.
// MODE 0: g_X = relu(x@W0 + b), copy to g_X0.  (A = Aext fp32, K=128)
// MODE 1: g_X = relu(c0*Xi + c1*(Xi@W)).        (A = g_Xi fp32, K=64)
template <int K, int MODE>
__global__ void __launch_bounds__(256) tc_gemm_k(
    const float* __restrict__ Aext, const float* __restrict__ W,
    const float* __restrict__ bias, float c0, float c1)
{
    constexpr int KP = K + 8;          // half lds (mult of 8)
    constexpr int WLD = 72;            // W lds (mult of 8)
    constexpr int CLD = 68;            // C lds floats (mult of 4)
    constexpr int A_BYTES = 64 * KP * 2;
    constexpr int W_BYTES = K * WLD * 2;
    __shared__ __align__(16) unsigned char sbuf[A_BYTES + W_BYTES];
    __half* Ash = (__half*)sbuf;
    __half* Wsh = (__half*)(sbuf + A_BYTES);
    float*  Csh = (float*)sbuf;        // aliases Ash AFTER the mma loop

    const float* A = (MODE == 0) ? Aext : g_Xi;
    int tid = threadIdx.x;
    int wid = tid >> 5;
    int row0 = blockIdx.x * 64;

    // Stage A (fp32 -> fp16), 64 x K
    for (int idx = tid; idx < 64 * (K / 4); idx += 256) {
        int r = idx / (K / 4), c4 = idx - r * (K / 4);
        int row = row0 + r;
        float4 v = make_float4(0.f, 0.f, 0.f, 0.f);
        if (row < N_V) v = *(const float4*)&A[(size_t)row * K + c4 * 4];
        __half2 h0 = __floats2half2_rn(v.x, v.y);
        __half2 h1 = __floats2half2_rn(v.z, v.w);
        *(uint2*)&Ash[r * KP + c4 * 4] = make_uint2(*(unsigned*)&h0, *(unsigned*)&h1);
    }
    // Stage W (fp32 -> fp16), K x 64
    for (int idx = tid; idx < K * 16; idx += 256) {
        int k = idx >> 4, c4 = idx & 15;
        float4 v = *(const float4*)&W[k * 64 + c4 * 4];
        __half2 h0 = __floats2half2_rn(v.x, v.y);
        __half2 h1 = __floats2half2_rn(v.z, v.w);
        *(uint2*)&Wsh[k * WLD + c4 * 4] = make_uint2(*(unsigned*)&h0, *(unsigned*)&h1);
    }
    __syncthreads();

    int tr  = (wid * 2) >> 2;
    int tc0 = (wid * 2) & 3;

    wmma::fragment<wmma::accumulator, 16, 16, 16, float> cf0, cf1;
    wmma::fill_fragment(cf0, 0.f);
    wmma::fill_fragment(cf1, 0.f);
    #pragma unroll
    for (int kk = 0; kk < K; kk += 16) {
        wmma::fragment<wmma::matrix_a, 16, 16, 16, __half, wmma::row_major> af;
        wmma::fragment<wmma::matrix_b, 16, 16, 16, __half, wmma::row_major> bf0, bf1;
        wmma::load_matrix_sync(af, Ash + tr * 16 * KP + kk, KP);
        wmma::load_matrix_sync(bf0, Wsh + kk * WLD + tc0 * 16, WLD);
        wmma::load_matrix_sync(bf1, Wsh + kk * WLD + (tc0 + 1) * 16, WLD);
        wmma::mma_sync(cf0, af, bf0, cf0);
        wmma::mma_sync(cf1, af, bf1, cf1);
    }
    __syncthreads();   // done reading Ash/Wsh; safe to alias Csh

    wmma::store_matrix_sync(Csh + tr * 16 * CLD + tc0 * 16,       cf0, CLD, wmma::mem_row_major);
    wmma::store_matrix_sync(Csh + tr * 16 * CLD + (tc0 + 1) * 16, cf1, CLD, wmma::mem_row_major);
    __syncthreads();

    // fp32 epilogue
    for (int idx = tid; idx < 64 * 16; idx += 256) {
        int r = idx >> 4, c4 = idx & 15;
        int row = row0 + r;
        if (row >= N_V) continue;
        float4 cv = *(float4*)&Csh[r * CLD + c4 * 4];
        float4 o;
        if (MODE == 0) {
            float4 b = *(const float4*)&bias[c4 * 4];
            o.x = fmaxf(cv.x + b.x, 0.f);
            o.y = fmaxf(cv.y + b.y, 0.f);
            o.z = fmaxf(cv.z + b.z, 0.f);
            o.w = fmaxf(cv.w + b.w, 0.f);
            *(float4*)&g_X [(size_t)row * NHID_ + c4 * 4] = o;
            *(float4*)&g_X0[(size_t)row * NHID_ + c4 * 4] = o;
        } else {
            float4 xi = *(const float4*)&g_Xi[(size_t)row * NHID_ + c4 * 4];
            o.x = fmaxf(c0 * xi.x + c1 * cv.x, 0.f);
            o.y = fmaxf(c0 * xi.y + c1 * cv.y, 0.f);
            o.z = fmaxf(c0 * xi.z + c1 * cv.z, 0.f);
            o.w = fmaxf(c0 * xi.w + c1 * cv.w, 0.f);
            *(float4*)&g_X[(size_t)row * NHID_ + c4 * 4] = o;
        }
    }
}

// ---------------- tensor-core output GEMM + fused log_softmax ----------------
// out = log_softmax(g_X @ Wout + bout); K=64, 40 real cols staged into a
// zero-padded 64-col fp16 W tile. fp32 accumulate + fp32 softmax epilogue.
__global__ void __launch_bounds__(256) tc_gemm_out_k(
    const float* __restrict__ W, const float* __restrict__ bias,
    float* __restrict__ outext)
{
    constexpr int K = 64;
    constexpr int KP = K + 8;
    constexpr int WLD = 72;
    constexpr int CLD = 68;
    constexpr int A_BYTES = 64 * KP * 2;
    constexpr int W_BYTES = K * WLD * 2;
    __shared__ __align__(16) unsigned char sbuf[A_BYTES + W_BYTES];
    __half* Ash = (__half*)sbuf;
    __half* Wsh = (__half*)(sbuf + A_BYTES);
    float*  Csh = (float*)sbuf;        // aliases after mma

    int tid = threadIdx.x;
    int wid = tid >> 5;
    int row0 = blockIdx.x * 64;

    // Stage A = g_X (fp32 -> fp16), 64 x 64
    for (int idx = tid; idx < 64 * 16; idx += 256) {
        int r = idx >> 4, c4 = idx & 15;
        int row = row0 + r;
        float4 v = make_float4(0.f, 0.f, 0.f, 0.f);
        if (row < N_V) v = *(const float4*)&g_X[(size_t)row * K + c4 * 4];
        __half2 h0 = __floats2half2_rn(v.x, v.y);
        __half2 h1 = __floats2half2_rn(v.z, v.w);
        *(uint2*)&Ash[r * KP + c4 * 4] = make_uint2(*(unsigned*)&h0, *(unsigned*)&h1);
    }
    // Stage W (K x 40 -> K x 64, zero-padded)
    for (int idx = tid; idx < K * 16; idx += 256) {
        int k = idx >> 4, c4 = idx & 15;
        float4 v = make_float4(0.f, 0.f, 0.f, 0.f);
        int c = c4 * 4;
        if (c + 3 < NCLASS_) v = *(const float4*)&W[k * NCLASS_ + c];
        else {
            if (c + 0 < NCLASS_) v.x = W[k * NCLASS_ + c + 0];
            if (c + 1 < NCLASS_) v.y = W[k * NCLASS_ + c + 1];
            if (c + 2 < NCLASS_) v.z = W[k * NCLASS_ + c + 2];
            if (c + 3 < NCLASS_) v.w = W[k * NCLASS_ + c + 3];
        }
        __half2 h0 = __floats2half2_rn(v.x, v.y);
        __half2 h1 = __floats2half2_rn(v.z, v.w);
        *(uint2*)&Wsh[k * WLD + c4 * 4] = make_uint2(*(unsigned*)&h0, *(unsigned*)&h1);
    }
    __syncthreads();

    int tr  = (wid * 2) >> 2;
    int tc0 = (wid * 2) & 3;

    wmma::fragment<wmma::accumulator, 16, 16, 16, float> cf0, cf1;
    wmma::fill_fragment(cf0, 0.f);
    wmma::fill_fragment(cf1, 0.f);
    #pragma unroll
    for (int kk = 0; kk < K; kk += 16) {
        wmma::fragment<wmma::matrix_a, 16, 16, 16, __half, wmma::row_major> af;
        wmma::fragment<wmma::matrix_b, 16, 16, 16, __half, wmma::row_major> bf0, bf1;
        wmma::load_matrix_sync(af, Ash + tr * 16 * KP + kk, KP);
        wmma::load_matrix_sync(bf0, Wsh + kk * WLD + tc0 * 16, WLD);
        wmma::load_matrix_sync(bf1, Wsh + kk * WLD + (tc0 + 1) * 16, WLD);
        wmma::mma_sync(cf0, af, bf0, cf0);
        wmma::mma_sync(cf1, af, bf1, cf1);
    }
    __syncthreads();

    wmma::store_matrix_sync(Csh + tr * 16 * CLD + tc0 * 16,       cf0, CLD, wmma::mem_row_major);
    wmma::store_matrix_sync(Csh + tr * 16 * CLD + (tc0 + 1) * 16, cf1, CLD, wmma::mem_row_major);
    __syncthreads();

    // fp32 log_softmax epilogue (one thread per row over the 40 real cols)
    if (tid < 64) {
        int row = row0 + tid;
        if (row < N_V) {
            float l[NCLASS_];
            float mx = -1e30f;
            #pragma unroll
            for (int c = 0; c < NCLASS_; c++) {
                l[c] = Csh[tid * CLD + c] + __ldg(bias + c);
                mx = fmaxf(mx, l[c]);
            }
            float s = 0.f;
            #pragma unroll
            for (int c = 0; c < NCLASS_; c++) s += __expf(l[c] - mx);
            float lse = mx + __logf(s);
            #pragma unroll
            for (int c = 0; c < NCLASS_; c++)
                outext[(size_t)row * NCLASS_ + c] = l[c] - lse;
        }
    }
}

// ---------------- launch ----------------
extern "C" void kernel_launch(void* const* d_in, const int* in_sizes, int n_in,
                              void* d_out, int out_size)
{
    const float* x    = (const float*)d_in[0];
    const float* degE = (const float*)d_in[1];
    const float* degV = (const float*)d_in[2];
    const float* W0   = (const float*)d_in[3];
    const float* b0   = (const float*)d_in[4];
    const float* Ws   = (const float*)d_in[5];
    const float* Wout = (const float*)d_in[6];
    const float* bout = (const float*)d_in[7];
    const int* vertex = (const int*)d_in[8];
    const int* edges  = (const int*)d_in[9];
    float* out = (float*)d_out;

    (void)in_sizes; (void)n_in; (void)out_size;

    const int GB = (N_V + 63) / 64;
    const int Q8 = NNZ_ / 8;

    // CSR/CSC build
    zero_cnt_k<<<(N_V + 255) / 256, 256>>>();
    hist_k<<<(Q8 + 255) / 256, 256>>>((const int4*)vertex, (const int4*)edges);
    alloc_k<<<(NE_ + N_V + 255) / 256, 256>>>(degE);
    build_adj_k<<<(Q8 + 255) / 256, 256>>>((const int4*)vertex, (const int4*)edges);

    // X = relu(x @ W0 + b0); X0 = X   (tensor core, 64-row tiles)
    tc_gemm_k<128, 0><<<GB, 256>>>(x, W0, b0, 0.f, 0.f);

    for (int i = 0; i < NLAYER_; i++) {
        float beta = logf(0.5f / (float)(i + 1) + 1.0f);
        agg_ve_k<<<(NE_ + 7) / 8, 256>>>();
        agg_ev_k<<<(N_V + 7) / 8, 256>>>(degV);
        tc_gemm_k<64, 1><<<GB, 256>>>(nullptr, Ws + (size_t)i * NHID_ * NHID_,
                                      nullptr, 1.0f - beta, beta);
    }

    // log_softmax(X @ Wout + bout)  (tensor core + fp32 softmax)
    tc_gemm_out_k<<<GB, 256>>>(Wout, bout, out);
}